// round 1
// baseline (speedup 1.0000x reference)
#include <cuda_runtime.h>

#define BB 16
#define NN 4096
#define DD 768
#define MM 8
#define BN (BB*NN)
#define NCHUNK 32
#define NC (NN/NCHUNK)   // 128
#define LN_EPS 1e-3f
// 1/sqrt(768)
#define SIM_SCALE 0.03608439182435161f

// ---------------- device scratch (no allocations allowed) ----------------
__device__ float g_qg[MM*DD];          // q*gamma
__device__ float g_qgsum[MM];          // sum_d q*gamma
__device__ float g_qb[MM];             // sum_d q*beta
__device__ float g_sim[BB*MM*NN];      // logits, overwritten in-place with w = attn*rstd
__device__ float g_mu[BN];
__device__ float g_rstd[BN];
__device__ float g_c[BB*MM];           // sum_n w*mu
__device__ float g_part[BB*NCHUNK*MM*DD]; // partial weighted sums

__device__ __forceinline__ float warp_allreduce_sum(float v) {
#pragma unroll
    for (int o = 16; o > 0; o >>= 1) v += __shfl_xor_sync(0xffffffffu, v, o);
    return v;
}

// ---------------- K0: precompute qg, qgsum, qb ----------------
__global__ void k0_prep(const float* __restrict__ q,
                        const float* __restrict__ gamma,
                        const float* __restrict__ beta) {
    int m = blockIdx.x;
    int t = threadIdx.x;
    float s1 = 0.f, s2 = 0.f;
    for (int d = t; d < DD; d += 256) {
        float qq = q[m * DD + d];
        float qg = qq * gamma[d];
        g_qg[m * DD + d] = qg;
        s1 += qg;
        s2 += qq * beta[d];
    }
    __shared__ float r1[256], r2[256];
    r1[t] = s1; r2[t] = s2;
    __syncthreads();
    for (int s = 128; s > 0; s >>= 1) {
        if (t < s) { r1[t] += r1[t + s]; r2[t] += r2[t + s]; }
        __syncthreads();
    }
    if (t == 0) { g_qgsum[m] = r1[0]; g_qb[m] = r2[0]; }
}

// ---------------- K1: LayerNorm stats + 8 query dots per row ----------------
// One warp handles 2 rows (amortizes qg smem traffic). CTA = 8 warps = 16 rows.
__global__ __launch_bounds__(256) void k1_ln_logits(const float* __restrict__ x) {
    __shared__ float4 qg_s[MM * DD / 4];  // 1536 float4 = 24KB
    int t = threadIdx.x;
    const float4* qg4 = (const float4*)g_qg;
    for (int i = t; i < MM * DD / 4; i += 256) qg_s[i] = qg4[i];
    __syncthreads();

    int warp = t >> 5, lane = t & 31;
    int r0 = blockIdx.x * 16 + warp * 2;   // even row; r0 and r0+1 same batch
    const float4* x4 = (const float4*)x;

    float4 xa[6], xb[6];
#pragma unroll
    for (int k = 0; k < 6; k++) xa[k] = x4[(size_t)r0 * 192 + lane + 32 * k];
#pragma unroll
    for (int k = 0; k < 6; k++) xb[k] = x4[(size_t)(r0 + 1) * 192 + lane + 32 * k];

    float s1a = 0.f, s2a = 0.f, s1b = 0.f, s2b = 0.f;
#pragma unroll
    for (int k = 0; k < 6; k++) {
        s1a += xa[k].x + xa[k].y + xa[k].z + xa[k].w;
        s2a += xa[k].x * xa[k].x + xa[k].y * xa[k].y + xa[k].z * xa[k].z + xa[k].w * xa[k].w;
        s1b += xb[k].x + xb[k].y + xb[k].z + xb[k].w;
        s2b += xb[k].x * xb[k].x + xb[k].y * xb[k].y + xb[k].z * xb[k].z + xb[k].w * xb[k].w;
    }

    float da[MM], db[MM];
#pragma unroll
    for (int m = 0; m < MM; m++) {
        float sa = 0.f, sb = 0.f;
#pragma unroll
        for (int k = 0; k < 6; k++) {
            float4 qv = qg_s[m * 192 + lane + 32 * k];
            sa += qv.x * xa[k].x + qv.y * xa[k].y + qv.z * xa[k].z + qv.w * xa[k].w;
            sb += qv.x * xb[k].x + qv.y * xb[k].y + qv.z * xb[k].z + qv.w * xb[k].w;
        }
        da[m] = sa; db[m] = sb;
    }

    // butterfly all-reduce (every lane gets full sums)
    s1a = warp_allreduce_sum(s1a);
    s2a = warp_allreduce_sum(s2a);
    s1b = warp_allreduce_sum(s1b);
    s2b = warp_allreduce_sum(s2b);
#pragma unroll
    for (int m = 0; m < MM; m++) {
        da[m] = warp_allreduce_sum(da[m]);
        db[m] = warp_allreduce_sum(db[m]);
    }

    const float invD = 1.f / (float)DD;
    float mua = s1a * invD, mub = s1b * invD;
    float ra = rsqrtf(s2a * invD - mua * mua + LN_EPS);
    float rb = rsqrtf(s2b * invD - mub * mub + LN_EPS);

    if (lane == 0) {
        g_mu[r0] = mua;   g_rstd[r0] = ra;
        g_mu[r0 + 1] = mub; g_rstd[r0 + 1] = rb;
    }

    int b0 = r0 >> 12;        // r0 / 4096
    int n0 = r0 & (NN - 1);   // r0 % 4096

    float qs = 0.f, qbv = 0.f;
    if (lane < MM) { qs = g_qgsum[lane]; qbv = g_qb[lane]; }

#pragma unroll
    for (int m = 0; m < MM; m++) {
        if (lane == m) {
            size_t base = ((size_t)(b0 * MM + m)) * NN + n0;
            g_sim[base]     = SIM_SCALE * (ra * (da[m] - mua * qs) + qbv);
            g_sim[base + 1] = SIM_SCALE * (rb * (db[m] - mub * qs) + qbv);
        }
    }
}

// ---------------- K2: softmax over N, fold in rstd, compute c ----------------
__global__ __launch_bounds__(256) void k2_softmax() {
    int bm = blockIdx.x;          // b*MM + m
    int b = bm >> 3;
    int t = threadIdx.x;
    float* row = g_sim + (size_t)bm * NN;

    float v[16];
    float mx = -1e30f;
#pragma unroll
    for (int i = 0; i < 16; i++) {
        v[i] = row[t + 256 * i];
        mx = fmaxf(mx, v[i]);
    }

    __shared__ float sred[256];
    sred[t] = mx; __syncthreads();
    for (int s = 128; s > 0; s >>= 1) {
        if (t < s) sred[t] = fmaxf(sred[t], sred[t + s]);
        __syncthreads();
    }
    mx = sred[0]; __syncthreads();

    float sum = 0.f;
#pragma unroll
    for (int i = 0; i < 16; i++) {
        v[i] = __expf(v[i] - mx);
        sum += v[i];
    }
    sred[t] = sum; __syncthreads();
    for (int s = 128; s > 0; s >>= 1) {
        if (t < s) sred[t] += sred[t + s];
        __syncthreads();
    }
    float inv = 1.f / sred[0]; __syncthreads();

    float cacc = 0.f;
#pragma unroll
    for (int i = 0; i < 16; i++) {
        int n = t + 256 * i;
        float w = v[i] * inv * g_rstd[b * NN + n];
        row[n] = w;                      // in-place: sim -> w
        cacc += w * g_mu[b * NN + n];
    }
    sred[t] = cacc; __syncthreads();
    for (int s = 128; s > 0; s >>= 1) {
        if (t < s) sred[t] += sred[t + s];
        __syncthreads();
    }
    if (t == 0) g_c[bm] = sred[0];
}

// ---------------- K3: partial weighted sums out_part[m,d] = sum_n w*x ----------------
// CTA handles (batch, N-chunk of 128 rows), full D. Thread t owns d = {t, t+256, t+512}.
__global__ __launch_bounds__(256) void k3_wsum(const float* __restrict__ x) {
    int b  = blockIdx.x / NCHUNK;
    int ch = blockIdx.x % NCHUNK;
    int t = threadIdx.x;
    int n0 = ch * NC;

    __shared__ float ws[MM][NC];   // 4KB, broadcast access
#pragma unroll
    for (int m = 0; m < MM; m++) {
        if (t < NC) ws[m][t] = g_sim[((size_t)(b * MM + m)) * NN + n0 + t];
    }
    __syncthreads();

    float acc[MM][3];
#pragma unroll
    for (int m = 0; m < MM; m++)
#pragma unroll
        for (int j = 0; j < 3; j++) acc[m][j] = 0.f;

    const float* xb = x + ((size_t)b * NN + n0) * DD;
#pragma unroll 2
    for (int n = 0; n < NC; n++) {
        float x0 = xb[(size_t)n * DD + t];
        float x1 = xb[(size_t)n * DD + t + 256];
        float x2 = xb[(size_t)n * DD + t + 512];
#pragma unroll
        for (int m = 0; m < MM; m++) {
            float w = ws[m][n];
            acc[m][0] += w * x0;
            acc[m][1] += w * x1;
            acc[m][2] += w * x2;
        }
    }

    float* p = g_part + ((size_t)(b * NCHUNK + ch)) * MM * DD;
#pragma unroll
    for (int m = 0; m < MM; m++) {
        p[m * DD + t]       = acc[m][0];
        p[m * DD + t + 256] = acc[m][1];
        p[m * DD + t + 512] = acc[m][2];
    }
}

// ---------------- K4: reduce partials, apply gamma/beta and -c ----------------
__global__ __launch_bounds__(256) void k4_final(const float* __restrict__ gamma,
                                                const float* __restrict__ beta,
                                                float* __restrict__ out) {
    int bm = blockIdx.x;
    int b = bm >> 3, m = bm & 7;
    int t = threadIdx.x;
    float c = g_c[bm];
#pragma unroll
    for (int j = 0; j < 3; j++) {
        int d = t + 256 * j;
        float s = 0.f;
#pragma unroll
        for (int ch = 0; ch < NCHUNK; ch++)
            s += g_part[((size_t)(b * NCHUNK + ch) * MM + m) * DD + d];
        out[(size_t)bm * DD + d] = gamma[d] * (s - c) + beta[d];
    }
}

extern "C" void kernel_launch(void* const* d_in, const int* in_sizes, int n_in,
                              void* d_out, int out_size) {
    const float* x     = (const float*)d_in[0];
    const float* q     = (const float*)d_in[1];
    const float* gamma = (const float*)d_in[2];
    const float* beta  = (const float*)d_in[3];
    float* out = (float*)d_out;

    k0_prep<<<MM, 256>>>(q, gamma, beta);
    k1_ln_logits<<<BN / 16, 256>>>(x);
    k2_softmax<<<BB * MM, 256>>>();
    k3_wsum<<<BB * NCHUNK, 256>>>(x);
    k4_final<<<BB * MM, 256>>>(gamma, beta, out);
}

// round 2
// speedup vs baseline: 1.0032x; 1.0032x over previous
#include <cuda_runtime.h>

#define BB 16
#define NN 4096
#define DD 768
#define MM 8
#define BN (BB*NN)
#define NCHUNK 32
#define NC (NN/NCHUNK)   // 128
#define LN_EPS 1e-3f
// 1/sqrt(768)
#define SIM_SCALE 0.03608439182435161f

// ---------------- device scratch (no allocations allowed) ----------------
__device__ float g_qg[MM*DD];          // q*gamma
__device__ float g_qgsum[MM];          // sum_d q*gamma
__device__ float g_qb[MM];             // sum_d q*beta
__device__ float g_sim[BB*MM*NN];      // logits, overwritten in-place with w = attn*rstd
__device__ float g_mu[BN];
__device__ float g_rstd[BN];
__device__ float g_c[BB*MM];           // sum_n w*mu
__device__ float g_part[BB*NCHUNK*MM*DD]; // partial weighted sums

__device__ __forceinline__ float warp_allreduce_sum(float v) {
#pragma unroll
    for (int o = 16; o > 0; o >>= 1) v += __shfl_xor_sync(0xffffffffu, v, o);
    return v;
}

// ---------------- K0: precompute qg, qgsum, qb ----------------
__global__ void k0_prep(const float* __restrict__ q,
                        const float* __restrict__ gamma,
                        const float* __restrict__ beta) {
    int m = blockIdx.x;
    int t = threadIdx.x;
    float s1 = 0.f, s2 = 0.f;
    for (int d = t; d < DD; d += 256) {
        float qq = q[m * DD + d];
        float qg = qq * gamma[d];
        g_qg[m * DD + d] = qg;
        s1 += qg;
        s2 += qq * beta[d];
    }
    __shared__ float r1[256], r2[256];
    r1[t] = s1; r2[t] = s2;
    __syncthreads();
    for (int s = 128; s > 0; s >>= 1) {
        if (t < s) { r1[t] += r1[t + s]; r2[t] += r2[t + s]; }
        __syncthreads();
    }
    if (t == 0) { g_qgsum[m] = r1[0]; g_qb[m] = r2[0]; }
}

// ---------------- K1: LayerNorm stats + 8 query dots per row ----------------
// One warp handles 2 rows (amortizes qg smem traffic). CTA = 8 warps = 16 rows.
__global__ __launch_bounds__(256) void k1_ln_logits(const float* __restrict__ x) {
    __shared__ float4 qg_s[MM * DD / 4];  // 1536 float4 = 24KB
    int t = threadIdx.x;
    const float4* qg4 = (const float4*)g_qg;
    for (int i = t; i < MM * DD / 4; i += 256) qg_s[i] = qg4[i];
    __syncthreads();

    int warp = t >> 5, lane = t & 31;
    int r0 = blockIdx.x * 16 + warp * 2;   // even row; r0 and r0+1 same batch
    const float4* x4 = (const float4*)x;

    float4 xa[6], xb[6];
#pragma unroll
    for (int k = 0; k < 6; k++) xa[k] = x4[(size_t)r0 * 192 + lane + 32 * k];
#pragma unroll
    for (int k = 0; k < 6; k++) xb[k] = x4[(size_t)(r0 + 1) * 192 + lane + 32 * k];

    float s1a = 0.f, s2a = 0.f, s1b = 0.f, s2b = 0.f;
#pragma unroll
    for (int k = 0; k < 6; k++) {
        s1a += xa[k].x + xa[k].y + xa[k].z + xa[k].w;
        s2a += xa[k].x * xa[k].x + xa[k].y * xa[k].y + xa[k].z * xa[k].z + xa[k].w * xa[k].w;
        s1b += xb[k].x + xb[k].y + xb[k].z + xb[k].w;
        s2b += xb[k].x * xb[k].x + xb[k].y * xb[k].y + xb[k].z * xb[k].z + xb[k].w * xb[k].w;
    }

    float da[MM], db[MM];
#pragma unroll
    for (int m = 0; m < MM; m++) {
        float sa = 0.f, sb = 0.f;
#pragma unroll
        for (int k = 0; k < 6; k++) {
            float4 qv = qg_s[m * 192 + lane + 32 * k];
            sa += qv.x * xa[k].x + qv.y * xa[k].y + qv.z * xa[k].z + qv.w * xa[k].w;
            sb += qv.x * xb[k].x + qv.y * xb[k].y + qv.z * xb[k].z + qv.w * xb[k].w;
        }
        da[m] = sa; db[m] = sb;
    }

    // butterfly all-reduce (every lane gets full sums)
    s1a = warp_allreduce_sum(s1a);
    s2a = warp_allreduce_sum(s2a);
    s1b = warp_allreduce_sum(s1b);
    s2b = warp_allreduce_sum(s2b);
#pragma unroll
    for (int m = 0; m < MM; m++) {
        da[m] = warp_allreduce_sum(da[m]);
        db[m] = warp_allreduce_sum(db[m]);
    }

    const float invD = 1.f / (float)DD;
    float mua = s1a * invD, mub = s1b * invD;
    float ra = rsqrtf(s2a * invD - mua * mua + LN_EPS);
    float rb = rsqrtf(s2b * invD - mub * mub + LN_EPS);

    if (lane == 0) {
        g_mu[r0] = mua;   g_rstd[r0] = ra;
        g_mu[r0 + 1] = mub; g_rstd[r0 + 1] = rb;
    }

    int b0 = r0 >> 12;        // r0 / 4096
    int n0 = r0 & (NN - 1);   // r0 % 4096

    float qs = 0.f, qbv = 0.f;
    if (lane < MM) { qs = g_qgsum[lane]; qbv = g_qb[lane]; }

#pragma unroll
    for (int m = 0; m < MM; m++) {
        if (lane == m) {
            size_t base = ((size_t)(b0 * MM + m)) * NN + n0;
            g_sim[base]     = SIM_SCALE * (ra * (da[m] - mua * qs) + qbv);
            g_sim[base + 1] = SIM_SCALE * (rb * (db[m] - mub * qs) + qbv);
        }
    }
}

// ---------------- K2: softmax over N, fold in rstd, compute c ----------------
__global__ __launch_bounds__(256) void k2_softmax() {
    int bm = blockIdx.x;          // b*MM + m
    int b = bm >> 3;
    int t = threadIdx.x;
    float* row = g_sim + (size_t)bm * NN;

    float v[16];
    float mx = -1e30f;
#pragma unroll
    for (int i = 0; i < 16; i++) {
        v[i] = row[t + 256 * i];
        mx = fmaxf(mx, v[i]);
    }

    __shared__ float sred[256];
    sred[t] = mx; __syncthreads();
    for (int s = 128; s > 0; s >>= 1) {
        if (t < s) sred[t] = fmaxf(sred[t], sred[t + s]);
        __syncthreads();
    }
    mx = sred[0]; __syncthreads();

    float sum = 0.f;
#pragma unroll
    for (int i = 0; i < 16; i++) {
        v[i] = __expf(v[i] - mx);
        sum += v[i];
    }
    sred[t] = sum; __syncthreads();
    for (int s = 128; s > 0; s >>= 1) {
        if (t < s) sred[t] += sred[t + s];
        __syncthreads();
    }
    float inv = 1.f / sred[0]; __syncthreads();

    float cacc = 0.f;
#pragma unroll
    for (int i = 0; i < 16; i++) {
        int n = t + 256 * i;
        float w = v[i] * inv * g_rstd[b * NN + n];
        row[n] = w;                      // in-place: sim -> w
        cacc += w * g_mu[b * NN + n];
    }
    sred[t] = cacc; __syncthreads();
    for (int s = 128; s > 0; s >>= 1) {
        if (t < s) sred[t] += sred[t + s];
        __syncthreads();
    }
    if (t == 0) g_c[bm] = sred[0];
}

// ---------------- K3: partial weighted sums out_part[m,d] = sum_n w*x ----------------
// CTA handles (batch, N-chunk of 128 rows), full D. Thread t owns d = {t, t+256, t+512}.
__global__ __launch_bounds__(256) void k3_wsum(const float* __restrict__ x) {
    int b  = blockIdx.x / NCHUNK;
    int ch = blockIdx.x % NCHUNK;
    int t = threadIdx.x;
    int n0 = ch * NC;

    __shared__ float ws[MM][NC];   // 4KB, broadcast access
#pragma unroll
    for (int m = 0; m < MM; m++) {
        if (t < NC) ws[m][t] = g_sim[((size_t)(b * MM + m)) * NN + n0 + t];
    }
    __syncthreads();

    float acc[MM][3];
#pragma unroll
    for (int m = 0; m < MM; m++)
#pragma unroll
        for (int j = 0; j < 3; j++) acc[m][j] = 0.f;

    const float* xb = x + ((size_t)b * NN + n0) * DD;
#pragma unroll 2
    for (int n = 0; n < NC; n++) {
        float x0 = xb[(size_t)n * DD + t];
        float x1 = xb[(size_t)n * DD + t + 256];
        float x2 = xb[(size_t)n * DD + t + 512];
#pragma unroll
        for (int m = 0; m < MM; m++) {
            float w = ws[m][n];
            acc[m][0] += w * x0;
            acc[m][1] += w * x1;
            acc[m][2] += w * x2;
        }
    }

    float* p = g_part + ((size_t)(b * NCHUNK + ch)) * MM * DD;
#pragma unroll
    for (int m = 0; m < MM; m++) {
        p[m * DD + t]       = acc[m][0];
        p[m * DD + t + 256] = acc[m][1];
        p[m * DD + t + 512] = acc[m][2];
    }
}

// ---------------- K4: reduce partials, apply gamma/beta and -c ----------------
__global__ __launch_bounds__(256) void k4_final(const float* __restrict__ gamma,
                                                const float* __restrict__ beta,
                                                float* __restrict__ out) {
    int bm = blockIdx.x;
    int b = bm >> 3, m = bm & 7;
    int t = threadIdx.x;
    float c = g_c[bm];
#pragma unroll
    for (int j = 0; j < 3; j++) {
        int d = t + 256 * j;
        float s = 0.f;
#pragma unroll
        for (int ch = 0; ch < NCHUNK; ch++)
            s += g_part[((size_t)(b * NCHUNK + ch) * MM + m) * DD + d];
        out[(size_t)bm * DD + d] = gamma[d] * (s - c) + beta[d];
    }
}

extern "C" void kernel_launch(void* const* d_in, const int* in_sizes, int n_in,
                              void* d_out, int out_size) {
    const float* x     = (const float*)d_in[0];
    const float* q     = (const float*)d_in[1];
    const float* gamma = (const float*)d_in[2];
    const float* beta  = (const float*)d_in[3];
    float* out = (float*)d_out;

    k0_prep<<<MM, 256>>>(q, gamma, beta);
    k1_ln_logits<<<BN / 16, 256>>>(x);
    k2_softmax<<<BB * MM, 256>>>();
    k3_wsum<<<BB * NCHUNK, 256>>>(x);
    k4_final<<<BB * MM, 256>>>(gamma, beta, out);
}

// round 3
// speedup vs baseline: 1.0161x; 1.0128x over previous
#include <cuda_runtime.h>

#define BB 16
#define NN 4096
#define DD 768
#define MM 8
#define BN (BB*NN)
#define NCHUNK 32
#define NC (NN/NCHUNK)   // 128
#define LN_EPS 1e-3f
// 1/sqrt(768)
#define SIM_SCALE 0.03608439182435161f

// ---------------- device scratch (no allocations allowed) ----------------
__device__ float g_qg[MM*DD];          // q*gamma
__device__ float g_qgsum[MM];          // sum_d q*gamma
__device__ float g_qb[MM];             // sum_d q*beta
__device__ float g_sim[BB*MM*NN];      // logits, overwritten in-place with w = attn*rstd
__device__ float g_mu[BN];
__device__ float g_rstd[BN];
__device__ float g_c[BB*MM];           // sum_n w*mu
__device__ float g_part[BB*NCHUNK*MM*DD]; // partial weighted sums

__device__ __forceinline__ float warp_allreduce_sum(float v) {
#pragma unroll
    for (int o = 16; o > 0; o >>= 1) v += __shfl_xor_sync(0xffffffffu, v, o);
    return v;
}

// ---------------- K0: precompute qg, qgsum, qb ----------------
__global__ void k0_prep(const float* __restrict__ q,
                        const float* __restrict__ gamma,
                        const float* __restrict__ beta) {
    int m = blockIdx.x;
    int t = threadIdx.x;
    float s1 = 0.f, s2 = 0.f;
    for (int d = t; d < DD; d += 256) {
        float qq = q[m * DD + d];
        float qg = qq * gamma[d];
        g_qg[m * DD + d] = qg;
        s1 += qg;
        s2 += qq * beta[d];
    }
    __shared__ float r1[256], r2[256];
    r1[t] = s1; r2[t] = s2;
    __syncthreads();
    for (int s = 128; s > 0; s >>= 1) {
        if (t < s) { r1[t] += r1[t + s]; r2[t] += r2[t + s]; }
        __syncthreads();
    }
    if (t == 0) { g_qgsum[m] = r1[0]; g_qb[m] = r2[0]; }
}

// ---------------- K1: LayerNorm stats + 8 query dots per row ----------------
// One warp handles 2 rows (amortizes qg smem traffic). CTA = 8 warps = 16 rows.
__global__ __launch_bounds__(256) void k1_ln_logits(const float* __restrict__ x) {
    __shared__ float4 qg_s[MM * DD / 4];  // 1536 float4 = 24KB
    int t = threadIdx.x;
    const float4* qg4 = (const float4*)g_qg;
    for (int i = t; i < MM * DD / 4; i += 256) qg_s[i] = qg4[i];
    __syncthreads();

    int warp = t >> 5, lane = t & 31;
    int r0 = blockIdx.x * 16 + warp * 2;   // even row; r0 and r0+1 same batch
    const float4* x4 = (const float4*)x;

    float4 xa[6], xb[6];
#pragma unroll
    for (int k = 0; k < 6; k++) xa[k] = x4[(size_t)r0 * 192 + lane + 32 * k];
#pragma unroll
    for (int k = 0; k < 6; k++) xb[k] = x4[(size_t)(r0 + 1) * 192 + lane + 32 * k];

    float s1a = 0.f, s2a = 0.f, s1b = 0.f, s2b = 0.f;
#pragma unroll
    for (int k = 0; k < 6; k++) {
        s1a += xa[k].x + xa[k].y + xa[k].z + xa[k].w;
        s2a += xa[k].x * xa[k].x + xa[k].y * xa[k].y + xa[k].z * xa[k].z + xa[k].w * xa[k].w;
        s1b += xb[k].x + xb[k].y + xb[k].z + xb[k].w;
        s2b += xb[k].x * xb[k].x + xb[k].y * xb[k].y + xb[k].z * xb[k].z + xb[k].w * xb[k].w;
    }

    float da[MM], db[MM];
#pragma unroll
    for (int m = 0; m < MM; m++) {
        float sa = 0.f, sb = 0.f;
#pragma unroll
        for (int k = 0; k < 6; k++) {
            float4 qv = qg_s[m * 192 + lane + 32 * k];
            sa += qv.x * xa[k].x + qv.y * xa[k].y + qv.z * xa[k].z + qv.w * xa[k].w;
            sb += qv.x * xb[k].x + qv.y * xb[k].y + qv.z * xb[k].z + qv.w * xb[k].w;
        }
        da[m] = sa; db[m] = sb;
    }

    // butterfly all-reduce (every lane gets full sums)
    s1a = warp_allreduce_sum(s1a);
    s2a = warp_allreduce_sum(s2a);
    s1b = warp_allreduce_sum(s1b);
    s2b = warp_allreduce_sum(s2b);
#pragma unroll
    for (int m = 0; m < MM; m++) {
        da[m] = warp_allreduce_sum(da[m]);
        db[m] = warp_allreduce_sum(db[m]);
    }

    const float invD = 1.f / (float)DD;
    float mua = s1a * invD, mub = s1b * invD;
    float ra = rsqrtf(s2a * invD - mua * mua + LN_EPS);
    float rb = rsqrtf(s2b * invD - mub * mub + LN_EPS);

    if (lane == 0) {
        g_mu[r0] = mua;   g_rstd[r0] = ra;
        g_mu[r0 + 1] = mub; g_rstd[r0 + 1] = rb;
    }

    int b0 = r0 >> 12;        // r0 / 4096
    int n0 = r0 & (NN - 1);   // r0 % 4096

    float qs = 0.f, qbv = 0.f;
    if (lane < MM) { qs = g_qgsum[lane]; qbv = g_qb[lane]; }

#pragma unroll
    for (int m = 0; m < MM; m++) {
        if (lane == m) {
            size_t base = ((size_t)(b0 * MM + m)) * NN + n0;
            g_sim[base]     = SIM_SCALE * (ra * (da[m] - mua * qs) + qbv);
            g_sim[base + 1] = SIM_SCALE * (rb * (db[m] - mub * qs) + qbv);
        }
    }
}

// ---------------- K2: softmax over N, fold in rstd, compute c ----------------
__global__ __launch_bounds__(256) void k2_softmax() {
    int bm = blockIdx.x;          // b*MM + m
    int b = bm >> 3;
    int t = threadIdx.x;
    float* row = g_sim + (size_t)bm * NN;

    float v[16];
    float mx = -1e30f;
#pragma unroll
    for (int i = 0; i < 16; i++) {
        v[i] = row[t + 256 * i];
        mx = fmaxf(mx, v[i]);
    }

    __shared__ float sred[256];
    sred[t] = mx; __syncthreads();
    for (int s = 128; s > 0; s >>= 1) {
        if (t < s) sred[t] = fmaxf(sred[t], sred[t + s]);
        __syncthreads();
    }
    mx = sred[0]; __syncthreads();

    float sum = 0.f;
#pragma unroll
    for (int i = 0; i < 16; i++) {
        v[i] = __expf(v[i] - mx);
        sum += v[i];
    }
    sred[t] = sum; __syncthreads();
    for (int s = 128; s > 0; s >>= 1) {
        if (t < s) sred[t] += sred[t + s];
        __syncthreads();
    }
    float inv = 1.f / sred[0]; __syncthreads();

    float cacc = 0.f;
#pragma unroll
    for (int i = 0; i < 16; i++) {
        int n = t + 256 * i;
        float w = v[i] * inv * g_rstd[b * NN + n];
        row[n] = w;                      // in-place: sim -> w
        cacc += w * g_mu[b * NN + n];
    }
    sred[t] = cacc; __syncthreads();
    for (int s = 128; s > 0; s >>= 1) {
        if (t < s) sred[t] += sred[t + s];
        __syncthreads();
    }
    if (t == 0) g_c[bm] = sred[0];
}

// ---------------- K3: partial weighted sums out_part[m,d] = sum_n w*x ----------------
// CTA handles (batch, N-chunk of 128 rows), full D. Thread t owns d = {t, t+256, t+512}.
__global__ __launch_bounds__(256) void k3_wsum(const float* __restrict__ x) {
    int b  = blockIdx.x / NCHUNK;
    int ch = blockIdx.x % NCHUNK;
    int t = threadIdx.x;
    int n0 = ch * NC;

    __shared__ float ws[MM][NC];   // 4KB, broadcast access
#pragma unroll
    for (int m = 0; m < MM; m++) {
        if (t < NC) ws[m][t] = g_sim[((size_t)(b * MM + m)) * NN + n0 + t];
    }
    __syncthreads();

    float acc[MM][3];
#pragma unroll
    for (int m = 0; m < MM; m++)
#pragma unroll
        for (int j = 0; j < 3; j++) acc[m][j] = 0.f;

    const float* xb = x + ((size_t)b * NN + n0) * DD;
#pragma unroll 2
    for (int n = 0; n < NC; n++) {
        float x0 = xb[(size_t)n * DD + t];
        float x1 = xb[(size_t)n * DD + t + 256];
        float x2 = xb[(size_t)n * DD + t + 512];
#pragma unroll
        for (int m = 0; m < MM; m++) {
            float w = ws[m][n];
            acc[m][0] += w * x0;
            acc[m][1] += w * x1;
            acc[m][2] += w * x2;
        }
    }

    float* p = g_part + ((size_t)(b * NCHUNK + ch)) * MM * DD;
#pragma unroll
    for (int m = 0; m < MM; m++) {
        p[m * DD + t]       = acc[m][0];
        p[m * DD + t + 256] = acc[m][1];
        p[m * DD + t + 512] = acc[m][2];
    }
}

// ---------------- K4: reduce partials, apply gamma/beta and -c ----------------
__global__ __launch_bounds__(256) void k4_final(const float* __restrict__ gamma,
                                                const float* __restrict__ beta,
                                                float* __restrict__ out) {
    int bm = blockIdx.x;
    int b = bm >> 3, m = bm & 7;
    int t = threadIdx.x;
    float c = g_c[bm];
#pragma unroll
    for (int j = 0; j < 3; j++) {
        int d = t + 256 * j;
        float s = 0.f;
#pragma unroll
        for (int ch = 0; ch < NCHUNK; ch++)
            s += g_part[((size_t)(b * NCHUNK + ch) * MM + m) * DD + d];
        out[(size_t)bm * DD + d] = gamma[d] * (s - c) + beta[d];
    }
}

extern "C" void kernel_launch(void* const* d_in, const int* in_sizes, int n_in,
                              void* d_out, int out_size) {
    const float* x     = (const float*)d_in[0];
    const float* q     = (const float*)d_in[1];
    const float* gamma = (const float*)d_in[2];
    const float* beta  = (const float*)d_in[3];
    float* out = (float*)d_out;

    k0_prep<<<MM, 256>>>(q, gamma, beta);
    k1_ln_logits<<<BN / 16, 256>>>(x);
    k2_softmax<<<BB * MM, 256>>>();
    k3_wsum<<<BB * NCHUNK, 256>>>(x);
    k4_final<<<BB * MM, 256>>>(gamma, beta, out);
}